// round 2
// baseline (speedup 1.0000x reference)
#include <cuda_runtime.h>
#include <math.h>

#define NN 4096
#define FF 320
#define MAXDEG 768

// ---------------- scratch (static __device__ globals; no allocations) ----------------
__device__ float g_Wh[NN * FF];
__device__ float g_org[NN * FF];
__device__ float g_D0[NN * FF];
__device__ float g_D1[NN * FF];
__device__ float g_bA[NN * FF];
__device__ float g_bB[NN * FF];
__device__ float g_cat[NN * 2 * FF];
__device__ float g_cent[NN];
__device__ float g_s1[NN];
__device__ float g_s2[NN];
__device__ float g_sc[NN];
__device__ int g_cols[NN * MAXDEG];
__device__ int g_deg[NN];
__device__ int g_idp[NN];
__device__ int g_p1[NN];
__device__ int g_p2[NN];
__device__ int g_pi1[NN];
__device__ int g_pi2[NN];
__device__ int g_i0[NN];
__device__ int g_i1[NN];

// ---------------- adjacency ELL build + degree centrality (warp per row) ----------------
__global__ void build_adj(const float* __restrict__ A, int* __restrict__ cols,
                          int* __restrict__ deg, float* __restrict__ cent) {
    int warp = (blockIdx.x * blockDim.x + threadIdx.x) >> 5;
    int lane = threadIdx.x & 31;
    if (warp >= NN) return;
    long rowoff = (long)warp * NN;
    float sum = 0.f;
    int base = 0;
    for (int c0 = 0; c0 < NN; c0 += 32) {
        float v = A[rowoff + c0 + lane];
        sum += v;
        unsigned m = __ballot_sync(0xffffffffu, v > 0.f);
        if (v > 0.f) {
            int pos = base + __popc(m & ((1u << lane) - 1u));
            if (pos < MAXDEG) cols[(long)warp * MAXDEG + pos] = c0 + lane;
        }
        base += __popc(m);
    }
    for (int o = 16; o; o >>= 1) sum += __shfl_xor_sync(0xffffffffu, sum, o);
    if (lane == 0) {
        deg[warp] = base < MAXDEG ? base : MAXDEG;
        cent[warp] = sum / (float)(NN - 1);
    }
}

__global__ void iota_k(int* p) {
    int i = blockIdx.x * blockDim.x + threadIdx.x;
    if (i < NN) p[i] = i;
}

// ---------------- GEMM: C = [X | cent*nc] @ W ; W is (K+nc) x FF row-major ----------------
#define BM 64
#define BN 64
#define BK 16
__global__ void gemm_xcent(const float* __restrict__ X, int ldX, int K, int nc,
                           const float* __restrict__ cent,
                           const float* __restrict__ W,
                           float* __restrict__ C) {
    __shared__ float As[BK][BM];
    __shared__ float Bs[BK][BN];
    int tid = threadIdx.x;
    int row0 = blockIdx.y * BM;
    int col0 = blockIdx.x * BN;
    int Ktot = K + nc;
    int tx = tid & 15, ty = tid >> 4;
    float acc[4][4];
#pragma unroll
    for (int i = 0; i < 4; i++)
#pragma unroll
        for (int j = 0; j < 4; j++) acc[i][j] = 0.f;

    for (int k0 = 0; k0 < Ktot; k0 += BK) {
#pragma unroll
        for (int l = 0; l < 4; l++) {
            int idx = tid + l * 256;
            int m = idx & 63, kk = idx >> 6;
            int k = k0 + kk;
            int r = row0 + m;
            float v = 0.f;
            if (k < K) v = X[(long)r * ldX + k];
            else if (k < Ktot) v = cent[r];
            As[kk][m] = v;
        }
#pragma unroll
        for (int l = 0; l < 4; l++) {
            int idx = tid + l * 256;
            int n = idx & 63, kk = idx >> 6;
            int k = k0 + kk;
            Bs[kk][n] = (k < Ktot) ? W[(long)k * FF + col0 + n] : 0.f;
        }
        __syncthreads();
#pragma unroll
        for (int kk = 0; kk < BK; kk++) {
            float ra[4], rb[4];
#pragma unroll
            for (int i = 0; i < 4; i++) ra[i] = As[kk][ty * 4 + i];
#pragma unroll
            for (int j = 0; j < 4; j++) rb[j] = Bs[kk][tx * 4 + j];
#pragma unroll
            for (int i = 0; i < 4; i++)
#pragma unroll
                for (int j = 0; j < 4; j++) acc[i][j] = fmaf(ra[i], rb[j], acc[i][j]);
        }
        __syncthreads();
    }
#pragma unroll
    for (int i = 0; i < 4; i++)
#pragma unroll
        for (int j = 0; j < 4; j++)
            C[(long)(row0 + ty * 4 + i) * FF + col0 + tx * 4 + j] = acc[i][j];
}

// ---------------- unpool: out[idx[i]][j] = X[i][j] * sigmoid((X @ W^T)[i][j] + b[j]) ----------------
__global__ void gemm_unpool(const float* __restrict__ X, const float* __restrict__ W,
                            const float* __restrict__ b, const int* __restrict__ idxArr,
                            float* __restrict__ out) {
    __shared__ float As[BK][BM];
    __shared__ float Bs[BK][BN];
    int tid = threadIdx.x;
    int row0 = blockIdx.y * BM;
    int col0 = blockIdx.x * BN;
    int tx = tid & 15, ty = tid >> 4;
    float acc[4][4];
#pragma unroll
    for (int i = 0; i < 4; i++)
#pragma unroll
        for (int j = 0; j < 4; j++) acc[i][j] = 0.f;

    for (int k0 = 0; k0 < FF; k0 += BK) {
#pragma unroll
        for (int l = 0; l < 4; l++) {
            int idx = tid + l * 256;
            int m = idx & 63, kk = idx >> 6;
            As[kk][m] = X[(long)(row0 + m) * FF + k0 + kk];
        }
#pragma unroll
        for (int l = 0; l < 4; l++) {
            int idx = tid + l * 256;
            int kk = idx & 15, n = idx >> 4;   // consecutive threads -> consecutive k (coalesced)
            Bs[kk][n] = W[(long)(col0 + n) * FF + k0 + kk];   // W^T access
        }
        __syncthreads();
#pragma unroll
        for (int kk = 0; kk < BK; kk++) {
            float ra[4], rb[4];
#pragma unroll
            for (int i = 0; i < 4; i++) ra[i] = As[kk][ty * 4 + i];
#pragma unroll
            for (int j = 0; j < 4; j++) rb[j] = Bs[kk][tx * 4 + j];
#pragma unroll
            for (int i = 0; i < 4; i++)
#pragma unroll
                for (int j = 0; j < 4; j++) acc[i][j] = fmaf(ra[i], rb[j], acc[i][j]);
        }
        __syncthreads();
    }
#pragma unroll
    for (int i = 0; i < 4; i++) {
        int r = row0 + ty * 4 + i;
        int dst = idxArr[r];
#pragma unroll
        for (int j = 0; j < 4; j++) {
            int c = col0 + tx * 4 + j;
            float aw = 1.f / (1.f + expf(-(acc[i][j] + b[c])));
            out[(long)dst * FF + c] = X[(long)r * FF + c] * aw;
        }
    }
}

// ---------------- s1/s2 = Wh @ a-halves (warp per row) ----------------
__global__ void compute_s(const float* __restrict__ Wh, const float* __restrict__ a,
                          float* __restrict__ s1, float* __restrict__ s2) {
    int warp = (blockIdx.x * blockDim.x + threadIdx.x) >> 5;
    int lane = threadIdx.x & 31;
    if (warp >= NN) return;
    float x1 = 0.f, x2 = 0.f;
    for (int t = lane; t < FF; t += 32) {
        float w = Wh[(long)warp * FF + t];
        x1 = fmaf(w, a[t], x1);
        x2 = fmaf(w, a[FF + t], x2);
    }
    for (int o = 16; o; o >>= 1) {
        x1 += __shfl_down_sync(0xffffffffu, x1, o);
        x2 += __shfl_down_sync(0xffffffffu, x2, o);
    }
    if (lane == 0) { s1[warp] = x1; s2[warp] = x2; }
}

// ---------------- pool scores: sigmoid((X@w + b)/100) (warp per row) ----------------
__global__ void scores_k(const float* __restrict__ X, const float* __restrict__ w,
                         const float* __restrict__ b, float* __restrict__ sc) {
    int warp = (blockIdx.x * blockDim.x + threadIdx.x) >> 5;
    int lane = threadIdx.x & 31;
    if (warp >= NN) return;
    float z = 0.f;
    for (int t = lane; t < FF; t += 32) z = fmaf(X[(long)warp * FF + t], w[t], z);
    for (int o = 16; o; o >>= 1) z += __shfl_down_sync(0xffffffffu, z, o);
    if (lane == 0) {
        float v = (z + b[0]) * 0.01f;
        sc[warp] = 1.f / (1.f + expf(-v));
    }
}

// ---------------- stable descending rank (top_k with k=N semantics) ----------------
__global__ void rank_kernel(const float* __restrict__ s, int* __restrict__ idxArr) {
    __shared__ int red[256];
    int i = blockIdx.x;
    int tid = threadIdx.x;
    float si = s[i];
    int cnt = 0;
    for (int j = tid; j < NN; j += 256) {
        float sj = s[j];
        cnt += (sj > si) || (sj == si && j < i);
    }
    red[tid] = cnt;
    __syncthreads();
    for (int st = 128; st > 0; st >>= 1) {
        if (tid < st) red[tid] += red[tid + st];
        __syncthreads();
    }
    if (tid == 0) idxArr[red[0]] = i;
}

// ---------------- apply pool: permute X*value, update perm + inverse ----------------
__global__ void pool_apply(const float* __restrict__ Xold, const float* __restrict__ sc,
                           const int* __restrict__ idxArr, const int* __restrict__ pOld,
                           int* __restrict__ pNew, int* __restrict__ pinvNew,
                           float* __restrict__ Xnew) {
    int r = blockIdx.x;
    int o = idxArr[r];
    if (threadIdx.x == 0) {
        int po = pOld[o];
        pNew[r] = po;
        pinvNew[po] = r;
    }
    float v = sc[o];
    for (int t = threadIdx.x; t < FF; t += blockDim.x)
        Xnew[(long)r * FF + t] = Xold[(long)o * FF + t] * v;
}

// ---------------- sparse GAT attention + aggregation (block per row) ----------------
__global__ void attn_kernel(const float* __restrict__ Wh, const float* __restrict__ s1,
                            const float* __restrict__ s2, const int* __restrict__ cols,
                            const int* __restrict__ deg, const int* __restrict__ p,
                            const int* __restrict__ pinv, float* __restrict__ out,
                            int applyElu) {
    __shared__ int nb[MAXDEG];
    __shared__ float ev[MAXDEG];
    __shared__ float red[256];
    int i = blockIdx.x;
    int tid = threadIdx.x;
    int orig = p[i];
    int d = deg[orig];
    float si = s1[i];
    for (int k = tid; k < d; k += 256) {
        int c = cols[(long)orig * MAXDEG + k];
        int r = pinv[c];
        nb[k] = r;
        float e = si + s2[r];
        ev[k] = e > 0.f ? e : 0.2f * e;   // leaky_relu(0.2)
    }
    __syncthreads();
    // max
    float m = -3.4e38f;
    for (int k = tid; k < d; k += 256) m = fmaxf(m, ev[k]);
    red[tid] = m;
    __syncthreads();
    for (int st = 128; st > 0; st >>= 1) {
        if (tid < st) red[tid] = fmaxf(red[tid], red[tid + st]);
        __syncthreads();
    }
    m = red[0];
    __syncthreads();
    // exp & sum
    float ssum = 0.f;
    for (int k = tid; k < d; k += 256) {
        float e = expf(ev[k] - m);
        ev[k] = e;
        ssum += e;
    }
    red[tid] = ssum;
    __syncthreads();
    for (int st = 128; st > 0; st >>= 1) {
        if (tid < st) red[tid] += red[tid + st];
        __syncthreads();
    }
    float inv = 1.f / red[0];
    __syncthreads();
    // aggregate hp[i] = sum_k att_k * Wh[nb_k]; unroll x4 over neighbors for ILP
    int d4 = d & ~3;
    for (int j = tid; j < FF; j += 256) {
        float acc0 = 0.f, acc1 = 0.f, acc2 = 0.f, acc3 = 0.f;
        int k = 0;
        for (; k < d4; k += 4) {
            acc0 = fmaf(ev[k],     Wh[(long)nb[k]     * FF + j], acc0);
            acc1 = fmaf(ev[k + 1], Wh[(long)nb[k + 1] * FF + j], acc1);
            acc2 = fmaf(ev[k + 2], Wh[(long)nb[k + 2] * FF + j], acc2);
            acc3 = fmaf(ev[k + 3], Wh[(long)nb[k + 3] * FF + j], acc3);
        }
        for (; k < d; k++) acc0 = fmaf(ev[k], Wh[(long)nb[k] * FF + j], acc0);
        float acc = (acc0 + acc1) + (acc2 + acc3);
        acc *= inv;
        if (applyElu) acc = acc > 0.f ? acc : expm1f(acc);
        out[(long)i * FF + j] = acc;
    }
}

// ---------------- small elementwise helpers ----------------
__global__ void add_k(float* __restrict__ dst, const float* __restrict__ src) {
    int i = blockIdx.x * blockDim.x + threadIdx.x;
    if (i < NN * FF) dst[i] += src[i];
}

__global__ void concat2(const float* __restrict__ a, const float* __restrict__ b,
                        float* __restrict__ out) {
    int idx = blockIdx.x * blockDim.x + threadIdx.x;
    if (idx >= NN * 2 * FF) return;
    int i = idx / (2 * FF), j = idx % (2 * FF);
    out[idx] = (j < FF) ? a[(long)i * FF + j] : b[(long)i * FF + j - FF];
}

// ---------------- host driver ----------------
static void* sym(const void* s) {
    void* p = nullptr;
    cudaGetSymbolAddress(&p, s);
    return p;
}

extern "C" void kernel_launch(void* const* d_in, const int* in_sizes, int n_in,
                              void* d_out, int out_size) {
    const float* A        = (const float*)d_in[0];
    const float* X        = (const float*)d_in[1];
    const float* start_W  = (const float*)d_in[2];
    const float* start_a  = (const float*)d_in[3];
    const float* bottom_W = (const float*)d_in[4];
    const float* bottom_a = (const float*)d_in[5];
    const float* end_W    = (const float*)d_in[6];
    const float* end_a    = (const float*)d_in[7];
    const float* down_W0  = (const float*)d_in[8];
    const float* down_a0  = (const float*)d_in[9];
    const float* up_W0    = (const float*)d_in[10];
    const float* up_a0    = (const float*)d_in[11];
    const float* pool_w0  = (const float*)d_in[12];
    const float* pool_b0  = (const float*)d_in[13];
    const float* unpool_w0= (const float*)d_in[14];
    const float* unpool_b0= (const float*)d_in[15];
    const float* down_W1  = (const float*)d_in[16];
    const float* down_a1  = (const float*)d_in[17];
    const float* up_W1    = (const float*)d_in[18];
    const float* up_a1    = (const float*)d_in[19];
    const float* pool_w1  = (const float*)d_in[20];
    const float* pool_b1  = (const float*)d_in[21];
    const float* unpool_w1= (const float*)d_in[22];
    const float* unpool_b1= (const float*)d_in[23];

    float* Wh   = (float*)sym(g_Wh);
    float* org  = (float*)sym(g_org);
    float* D0   = (float*)sym(g_D0);
    float* D1   = (float*)sym(g_D1);
    float* bA   = (float*)sym(g_bA);
    float* bB   = (float*)sym(g_bB);
    float* cat  = (float*)sym(g_cat);
    float* cent = (float*)sym(g_cent);
    float* s1   = (float*)sym(g_s1);
    float* s2   = (float*)sym(g_s2);
    float* sc   = (float*)sym(g_sc);
    int* cols = (int*)sym(g_cols);
    int* deg  = (int*)sym(g_deg);
    int* idp  = (int*)sym(g_idp);
    int* p1   = (int*)sym(g_p1);
    int* p2   = (int*)sym(g_p2);
    int* pi1  = (int*)sym(g_pi1);
    int* pi2  = (int*)sym(g_pi2);
    int* i0   = (int*)sym(g_i0);
    int* i1   = (int*)sym(g_i1);

    float* outX = (float*)d_out;

    dim3 gemmGrid(FF / BN, NN / BM);

    // adjacency + centrality + identity perm
    build_adj<<<NN / 8, 256>>>(A, cols, deg, cent);
    iota_k<<<NN / 256, 256>>>(idp);

    // start GAT: [X | cent | cent] @ start_W -> org (elu)
    gemm_xcent<<<gemmGrid, 256>>>(X, FF, FF, 2, cent, start_W, Wh);
    compute_s<<<NN / 8, 256>>>(Wh, start_a, s1, s2);
    attn_kernel<<<NN, 256>>>(Wh, s1, s2, cols, deg, idp, idp, org, 1);

    // down0 GAT (level 0) -> D0
    gemm_xcent<<<gemmGrid, 256>>>(org, FF, FF, 1, cent, down_W0, Wh);
    compute_s<<<NN / 8, 256>>>(Wh, down_a0, s1, s2);
    attn_kernel<<<NN, 256>>>(Wh, s1, s2, cols, deg, idp, idp, D0, 1);

    // pool 0
    scores_k<<<NN / 8, 256>>>(D0, pool_w0, pool_b0, sc);
    rank_kernel<<<NN, 256>>>(sc, i0);
    pool_apply<<<NN, 320>>>(D0, sc, i0, idp, p1, pi1, bA);

    // down1 GAT (level 1, perm p1) -> D1
    gemm_xcent<<<gemmGrid, 256>>>(bA, FF, FF, 1, cent, down_W1, Wh);
    compute_s<<<NN / 8, 256>>>(Wh, down_a1, s1, s2);
    attn_kernel<<<NN, 256>>>(Wh, s1, s2, cols, deg, p1, pi1, D1, 1);

    // pool 1
    scores_k<<<NN / 8, 256>>>(D1, pool_w1, pool_b1, sc);
    rank_kernel<<<NN, 256>>>(sc, i1);
    pool_apply<<<NN, 320>>>(D1, sc, i1, p1, p2, pi2, bA);

    // bottom GAT (level 2, perm p2) -> bB
    gemm_xcent<<<gemmGrid, 256>>>(bA, FF, FF, 1, cent, bottom_W, Wh);
    compute_s<<<NN / 8, 256>>>(Wh, bottom_a, s1, s2);
    attn_kernel<<<NN, 256>>>(Wh, s1, s2, cols, deg, p2, pi2, bB, 1);

    // unpool 0 (scatter via i1 -> level 1) : bA[i1[r]] = bB[r] * sigmoid(bB@w0^T + b0)
    gemm_unpool<<<gemmGrid, 256>>>(bB, unpool_w0, unpool_b0, i1, bA);

    // up0 GAT (level 1, perm p1) -> bB ; bB += D1
    gemm_xcent<<<gemmGrid, 256>>>(bA, FF, FF, 1, cent, up_W0, Wh);
    compute_s<<<NN / 8, 256>>>(Wh, up_a0, s1, s2);
    attn_kernel<<<NN, 256>>>(Wh, s1, s2, cols, deg, p1, pi1, bB, 1);
    add_k<<<(NN * FF + 255) / 256, 256>>>(bB, D1);

    // unpool 1 (scatter via i0 -> level 0)
    gemm_unpool<<<gemmGrid, 256>>>(bB, unpool_w1, unpool_b1, i0, bA);

    // up1 GAT (level 0, identity perm) -> bB ; bB += D0
    gemm_xcent<<<gemmGrid, 256>>>(bA, FF, FF, 1, cent, up_W1, Wh);
    compute_s<<<NN / 8, 256>>>(Wh, up_a1, s1, s2);
    attn_kernel<<<NN, 256>>>(Wh, s1, s2, cols, deg, idp, idp, bB, 1);
    add_k<<<(NN * FF + 255) / 256, 256>>>(bB, D0);

    // end GAT: [bB | org | cent] @ end_W, no elu -> d_out first half
    concat2<<<(NN * 2 * FF + 255) / 256, 256>>>(bB, org, cat);
    gemm_xcent<<<gemmGrid, 256>>>(cat, 2 * FF, 2 * FF, 1, cent, end_W, Wh);
    compute_s<<<NN / 8, 256>>>(Wh, end_a, s1, s2);
    attn_kernel<<<NN, 256>>>(Wh, s1, s2, cols, deg, idp, idp, outX, 0);

    // second output: start_out (== org)
    cudaMemcpyAsync(outX + (long)NN * FF, org, (long)NN * FF * sizeof(float),
                    cudaMemcpyDeviceToDevice);
}